// round 15
// baseline (speedup 1.0000x reference)
#include <cuda_runtime.h>
#include <cuda_fp16.h>
#include <cstdint>

// Problem constants
#define B_SZ   32768
#define N_VARS 64
#define H_SZ   64
#define N_DISC 16
#define TILE_M 256          // batch rows per CTA
#define G_NODES 8           // nodes per CTA (one per warp)
#define NODE_GROUPS 8       // 64 / 8
#define BTILES (B_SZ / TILE_M)   // 128
#define MTILES (TILE_M / 16)     // 16

// X tile in smem: fp16, padded row stride 72 halves (144B) -> conflict-free ldmatrix
#define XS_STRIDE 72
#define XROW_B (XS_STRIDE * 2)   // 144

// smem layout (bytes)
#define SM_X    0
#define SM_X_SZ (TILE_M * XROW_B)                        // 36864
#define SM_W2   (SM_X + SM_X_SZ)                         // 36864
#define SM_W2_SZ (G_NODES * H_SZ * 4)                    // 2048
#define SM_OUT  (SM_W2 + SM_W2_SZ)                       // 38912
#define SM_OUT_SZ (TILE_M * G_NODES * 4)                 // 4096
#define SM_TOTAL (SM_OUT + SM_OUT_SZ)                    // 43008 (x2 CTAs = 86KB)

__device__ __forceinline__ uint32_t h2_as_u32(__half2 h) {
    union { __half2 h; uint32_t u; } cvt;
    cvt.h = h;
    return cvt.u;
}
__device__ __forceinline__ uint32_t smem_u32(const void* p) {
    uint32_t a;
    asm("{ .reg .u64 t; cvta.to.shared.u64 t, %1; cvt.u32.u64 %0, t; }" : "=r"(a) : "l"(p));
    return a;
}
__device__ __forceinline__ void ldmatrix_x4(uint32_t r[4], uint32_t addr) {
    asm volatile("ldmatrix.sync.aligned.m8n8.x4.shared.b16 {%0,%1,%2,%3}, [%4];"
                 : "=r"(r[0]), "=r"(r[1]), "=r"(r[2]), "=r"(r[3]) : "r"(addr));
}
__device__ __forceinline__ void mma16816(float c[4], const uint32_t a[4],
                                         uint32_t b0, uint32_t b1) {
    asm volatile(
        "mma.sync.aligned.m16n8k16.row.col.f32.f16.f16.f32 "
        "{%0,%1,%2,%3}, {%4,%5,%6,%7}, {%8,%9}, {%0,%1,%2,%3};"
        : "+f"(c[0]), "+f"(c[1]), "+f"(c[2]), "+f"(c[3])
        : "r"(a[0]), "r"(a[1]), "r"(a[2]), "r"(a[3]), "r"(b0), "r"(b1));
}
__device__ __forceinline__ uint32_t gate2(float x, float y, bool disc) {
    if (disc) {
        x = x > 0.f ? 1.f : 0.f;
        y = y > 0.f ? 1.f : 0.f;
    }
    return h2_as_u32(__floats2half2_rn(x, y));
}

// ---------------- single fused kernel ----------------
// One warp == one node. B fragments built in-prologue from W1/adj (L2-shared).
// X tile converted fp32->gated fp16 in smem; 32 MMA/mtile; fused relu+W2 epilogue.
__global__ void __launch_bounds__(256, 2)
main_kernel(const float4* __restrict__ in4, const float* __restrict__ W1,
            const float* __restrict__ W2, const float* __restrict__ adj,
            float* __restrict__ out) {
    extern __shared__ char smem[];
    const int tid = threadIdx.x;
    const int lane = tid & 31, warp = tid >> 5;   // warp = node-in-group
    const int group = blockIdx.y;
    const int row0 = blockIdx.x * TILE_M;
    const int node = group * G_NODES + warp;

    float* w2s = (float*)(smem + SM_W2);
    float* outs = (float*)(smem + SM_OUT);

    // --- W2 for this group (512 floats) ---
    if (tid < 128)
        ((float4*)w2s)[tid] = ((const float4*)(W2 + group * G_NODES * H_SZ))[tid];

    // --- load X tile, apply straight-through gate, convert fp16 ---
    // each thread: 2 float4 in -> 1 uint4 (16B chunk) out; row stride 144B
    {
        __half2* xs = (__half2*)(smem + SM_X);
        (void)xs;
#pragma unroll
        for (int it = 0; it < 8; it++) {
            int idx = tid + it * 256;             // 0..2047 chunks
            int r = idx >> 3, j = idx & 7;        // row, 16B-chunk-in-row
            float4 v0 = in4[(size_t)(row0 + r) * 16 + j * 2];
            float4 v1 = in4[(size_t)(row0 + r) * 16 + j * 2 + 1];
            bool disc = (j * 8) < N_DISC;         // vars j*8..j*8+7
            uint4 o;
            o.x = gate2(v0.x, v0.y, disc);
            o.y = gate2(v0.z, v0.w, disc);
            o.z = gate2(v1.x, v1.y, disc);
            o.w = gate2(v1.z, v1.w, disc);
            *(uint4*)(smem + SM_X + r * XROW_B + j * 16) = o;
        }
    }

    // --- build this warp's B fragments from W1 + adjacency (64 regs) ---
    // frag element mapping (col-major B): h = nt*8 + lane/4, k0 = kt*16 + (lane%4)*2
    uint2 bf[4][8];
    {
        const float* wbase = W1 + (size_t)node * H_SZ * N_VARS;
        const float* arow = adj + node * N_VARS;
        const int lk = (lane & 3) * 2;
        const int lh = lane >> 2;
#pragma unroll
        for (int kt = 0; kt < 4; kt++) {
            const int k0 = kt * 16 + lk;
            float2 alo = *(const float2*)(arow + k0);
            float2 ahi = *(const float2*)(arow + k0 + 8);
            if (node == N_VARS - 1) {   // hidden_flag: last node keeps only feature 63
                alo.x = 0.f; alo.y = 0.f;
                ahi.x = 0.f;
                if (k0 + 9 != N_VARS - 1) ahi.y = 0.f;
            }
#pragma unroll
            for (int nt = 0; nt < 8; nt++) {
                const float* wr = wbase + (nt * 8 + lh) * N_VARS + k0;
                float2 wlo = *(const float2*)(wr);
                float2 whi = *(const float2*)(wr + 8);
                bf[kt][nt].x = h2_as_u32(__floats2half2_rn(wlo.x * alo.x, wlo.y * alo.y));
                bf[kt][nt].y = h2_as_u32(__floats2half2_rn(whi.x * ahi.x, whi.y * ahi.y));
            }
        }
    }
    __syncthreads();

    const uint32_t xsb = smem_u32(smem) + SM_X;
    const int mtx = lane >> 3, rowm = lane & 7;
    const int lq = lane & 3;       // quad col id
    const int lr = lane >> 2;      // row-in-8
    const uint32_t arow_off = (uint32_t)(((mtx & 1) * 8 + rowm) * XROW_B
                                         + ((mtx >> 1) * 8) * 2);

    // --- W2 in registers: per-lane pair for each ntile ---
    float2 w2r[8];
#pragma unroll
    for (int nt = 0; nt < 8; nt++)
        w2r[nt] = *(const float2*)&w2s[warp * H_SZ + nt * 8 + lq * 2];

#pragma unroll 1
    for (int mt = 0; mt < MTILES; mt++) {
        const uint32_t mbase = xsb + (uint32_t)(mt * 16 * XROW_B) + arow_off;

        uint32_t a[4][4];
#pragma unroll
        for (int kt = 0; kt < 4; kt++)
            ldmatrix_x4(a[kt], mbase + (uint32_t)(kt * 32));

        float s0 = 0.f, s1 = 0.f;
#pragma unroll
        for (int nt = 0; nt < 8; nt++) {
            float c[4] = {0.f, 0.f, 0.f, 0.f};
#pragma unroll
            for (int kt = 0; kt < 4; kt++)
                mma16816(c, a[kt], bf[kt][nt].x, bf[kt][nt].y);
            s0 = fmaf(fmaxf(c[0], 0.f), w2r[nt].x, s0);
            s0 = fmaf(fmaxf(c[1], 0.f), w2r[nt].y, s0);
            s1 = fmaf(fmaxf(c[2], 0.f), w2r[nt].x, s1);
            s1 = fmaf(fmaxf(c[3], 0.f), w2r[nt].y, s1);
        }
        s0 += __shfl_xor_sync(0xFFFFFFFF, s0, 1);
        s0 += __shfl_xor_sync(0xFFFFFFFF, s0, 2);
        s1 += __shfl_xor_sync(0xFFFFFFFF, s1, 1);
        s1 += __shfl_xor_sync(0xFFFFFFFF, s1, 2);
        if (lq == 0) {
            outs[(mt * 16 + lr) * G_NODES + warp] = s0;
            outs[(mt * 16 + lr + 8) * G_NODES + warp] = s1;
        }
    }
    __syncthreads();

    // --- coalesced store: 256 rows x 8 floats = 512 float4 ---
#pragma unroll
    for (int it = 0; it < 2; it++) {
        int idx = tid + it * 256;
        int r = idx >> 1, q = idx & 1;
        float4 v = ((const float4*)outs)[idx];
        *(float4*)(out + (size_t)(row0 + r) * N_VARS + group * G_NODES + q * 4) = v;
    }
}

// ---------------- launch ----------------
extern "C" void kernel_launch(void* const* d_in, const int* in_sizes, int n_in,
                              void* d_out, int out_size) {
    // metadata order: t, inputs, W1, W2, adjacency, discrete_mask
    const float* inputs = (const float*)d_in[1];
    const float* W1     = (const float*)d_in[2];
    const float* W2     = (const float*)d_in[3];
    const float* adj    = (const float*)d_in[4];
    float* out = (float*)d_out;

    static bool attr_set = false;
    if (!attr_set) {
        cudaFuncSetAttribute(main_kernel, cudaFuncAttributeMaxDynamicSharedMemorySize,
                             SM_TOTAL);
        attr_set = true;
    }

    main_kernel<<<dim3(BTILES, NODE_GROUPS), 256, SM_TOTAL>>>(
        (const float4*)inputs, W1, W2, adj, out);
}

// round 16
// speedup vs baseline: 1.1232x; 1.1232x over previous
#include <cuda_runtime.h>
#include <cuda_fp16.h>
#include <cstdint>

// Problem constants
#define B_SZ   32768
#define N_VARS 64
#define H_SZ   64
#define N_DISC 16
#define TILE_M 256          // batch rows per CTA
#define G_NODES 8           // nodes per CTA (one per warp)
#define NODE_GROUPS 8       // 64 / 8
#define BTILES (B_SZ / TILE_M)   // 128
#define MTILES (TILE_M / 16)     // 16

// X tile in smem: fp16, padded row stride 72 halves (144B) -> conflict-free ldmatrix
#define XS_STRIDE 72

// smem layout (bytes)
#define SM_X    0
#define SM_X_SZ (TILE_M * XS_STRIDE * 2)                 // 36864
#define SM_W2   (SM_X + SM_X_SZ)                         // 36864
#define SM_W2_SZ (G_NODES * H_SZ * 4)                    // 2048
#define SM_OUT  (SM_W2 + SM_W2_SZ)                       // 38912
#define SM_OUT_SZ (TILE_M * G_NODES * 4)                 // 4096
#define SM_TOTAL (SM_OUT + SM_OUT_SZ)                    // 43008

__device__ __half g_x16[(size_t)B_SZ * N_VARS];    // 4 MB fp16 gated inputs
// Pre-swizzled fp16 B fragments: [node][ktile(4)][ntile(8)][lane(32)] x uint2
__device__ uint2 g_wfrag[(size_t)N_VARS * 4 * 8 * 32];

__device__ __forceinline__ uint32_t h2_as_u32(__half2 h) {
    union { __half2 h; uint32_t u; } cvt;
    cvt.h = h;
    return cvt.u;
}
__device__ __forceinline__ uint32_t smem_u32(const void* p) {
    uint32_t a;
    asm("{ .reg .u64 t; cvta.to.shared.u64 t, %1; cvt.u32.u64 %0, t; }" : "=r"(a) : "l"(p));
    return a;
}
__device__ __forceinline__ void ldmatrix_x4(uint32_t r[4], uint32_t addr) {
    asm volatile("ldmatrix.sync.aligned.m8n8.x4.shared.b16 {%0,%1,%2,%3}, [%4];"
                 : "=r"(r[0]), "=r"(r[1]), "=r"(r[2]), "=r"(r[3]) : "r"(addr));
}
__device__ __forceinline__ void mma16816(float c[4], const uint32_t a[4],
                                         uint32_t b0, uint32_t b1) {
    asm volatile(
        "mma.sync.aligned.m16n8k16.row.col.f32.f16.f16.f32 "
        "{%0,%1,%2,%3}, {%4,%5,%6,%7}, {%8,%9}, {%0,%1,%2,%3};"
        : "+f"(c[0]), "+f"(c[1]), "+f"(c[2]), "+f"(c[3])
        : "r"(a[0]), "r"(a[1]), "r"(a[2]), "r"(a[3]), "r"(b0), "r"(b1));
}
__device__ __forceinline__ uint32_t gate2(float x, float y, bool disc) {
    if (disc) {
        x = x > 0.f ? 1.f : 0.f;
        y = y > 0.f ? 1.f : 0.f;
    }
    return h2_as_u32(__floats2half2_rn(x, y));
}

// ---------------- kernel 1: input convert (straight-through gate) ----------------
// 8 floats per thread: 2x LDG.128 -> 1x STG.128
__global__ void __launch_bounds__(256) cvt_kernel(const float4* __restrict__ in) {
    int i = blockIdx.x * 256 + threadIdx.x;      // 0..262143
    float4 v0 = in[i * 2 + 0];
    float4 v1 = in[i * 2 + 1];
    bool disc = ((i * 8) & (N_VARS - 1)) < N_DISC;   // 8-aligned; 16 % 8 == 0
    uint4 o;
    o.x = gate2(v0.x, v0.y, disc);
    o.y = gate2(v0.z, v0.w, disc);
    o.z = gate2(v1.x, v1.y, disc);
    o.w = gate2(v1.z, v1.w, disc);
    ((uint4*)g_x16)[i] = o;
}

// ---------------- prolog: build masked fp16 B fragments ----------------
__global__ void __launch_bounds__(256) wfrag_kernel(const float* __restrict__ W1,
                                                    const float* __restrict__ adj) {
    int idx = blockIdx.x * 256 + threadIdx.x;        // 65536 total
    int lane  = idx & 31;
    int ntile = (idx >> 5) & 7;
    int ktile = (idx >> 8) & 3;
    int node  = idx >> 10;
    int h  = ntile * 8 + (lane >> 2);
    int k0 = ktile * 16 + (lane & 3) * 2;

    const float* wrow = W1 + ((size_t)node * H_SZ + h) * N_VARS;
    float2 wlo = *(const float2*)(wrow + k0);
    float2 whi = *(const float2*)(wrow + k0 + 8);
    const float* arow = adj + node * N_VARS;
    float2 alo = *(const float2*)(arow + k0);
    float2 ahi = *(const float2*)(arow + k0 + 8);
    if (node == N_VARS - 1) {   // hidden_flag: last node keeps only feature 63
        alo.x = 0.f; alo.y = 0.f;
        ahi.x = 0.f;
        if (k0 + 9 != N_VARS - 1) ahi.y = 0.f;
    }
    uint2 r;
    r.x = h2_as_u32(__floats2half2_rn(wlo.x * alo.x, wlo.y * alo.y));
    r.y = h2_as_u32(__floats2half2_rn(whi.x * ahi.x, whi.y * ahi.y));
    g_wfrag[idx] = r;
}

// ---------------- main kernel ----------------
// One warp == one node. B tile (64x64 fp16) lives in 64 registers per lane.
__global__ void __launch_bounds__(256, 2)
main_kernel(const float* __restrict__ W2, float* __restrict__ out) {
    extern __shared__ char smem[];
    const int tid = threadIdx.x;
    const int lane = tid & 31, warp = tid >> 5;   // warp = node-in-group
    const int group = blockIdx.y;
    const int row0 = blockIdx.x * TILE_M;

    __half2* xs = (__half2*)(smem + SM_X);
    float* w2s = (float*)(smem + SM_W2);
    float* outs = (float*)(smem + SM_OUT);

    // --- B fragments for this warp's node: 64 regs (L2-resident source) ---
    uint2 bf[4][8];
    {
        const uint2* src = g_wfrag + ((size_t)(group * G_NODES + warp) * 4) * 8 * 32 + lane;
#pragma unroll
        for (int kt = 0; kt < 4; kt++)
#pragma unroll
            for (int nt = 0; nt < 8; nt++)
                bf[kt][nt] = src[(kt * 8 + nt) * 32];
    }

    // --- W2 for this group (512 floats) ---
    if (tid < 128)
        ((float4*)w2s)[tid] = ((const float4*)(W2 + group * G_NODES * H_SZ))[tid];

    // --- load X tile (already gated fp16): 16B chunks, swizzle-free padded rows ---
    {
        const uint4* xsrc = (const uint4*)(g_x16 + (size_t)row0 * N_VARS);
#pragma unroll
        for (int it = 0; it < 8; it++) {
            int idx = tid + it * 256;             // 0..2047 chunks
            int r = idx >> 3, j = idx & 7;
            uint4 v = xsrc[idx];
            *(uint4*)(smem + SM_X + r * (XS_STRIDE * 2) + j * 16) = v;
        }
    }
    __syncthreads();

    const uint32_t xsb = smem_u32(smem) + SM_X;
    const int mtx = lane >> 3, rowm = lane & 7;
    const int lq = lane & 3;       // quad col id
    const int lr = lane >> 2;      // row-in-8
    const uint32_t arow_off = (uint32_t)(((mtx & 1) * 8 + rowm) * (XS_STRIDE * 2)
                                         + ((mtx >> 1) * 8) * 2);

    // --- W2 hoisted to registers: per-lane pair for each ntile ---
    float2 w2r[8];
#pragma unroll
    for (int nt = 0; nt < 8; nt++)
        w2r[nt] = *(const float2*)&w2s[warp * H_SZ + nt * 8 + lq * 2];

#pragma unroll 1
    for (int mt = 0; mt < MTILES; mt++) {
        const uint32_t mbase = xsb + (uint32_t)(mt * 16 * (XS_STRIDE * 2)) + arow_off;

        // all K=64 A fragments for this mtile (4 x ldmatrix.x4)
        uint32_t a[4][4];
#pragma unroll
        for (int kt = 0; kt < 4; kt++)
            ldmatrix_x4(a[kt], mbase + (uint32_t)(kt * 16 * 2));

        float s0 = 0.f, s1 = 0.f;
#pragma unroll
        for (int nt = 0; nt < 8; nt++) {
            float c[4] = {0.f, 0.f, 0.f, 0.f};
#pragma unroll
            for (int kt = 0; kt < 4; kt++)
                mma16816(c, a[kt], bf[kt][nt].x, bf[kt][nt].y);
            // fused epilogue for this ntile (overlaps next ntile's MMA chain)
            s0 = fmaf(fmaxf(c[0], 0.f), w2r[nt].x, s0);
            s0 = fmaf(fmaxf(c[1], 0.f), w2r[nt].y, s0);
            s1 = fmaf(fmaxf(c[2], 0.f), w2r[nt].x, s1);
            s1 = fmaf(fmaxf(c[3], 0.f), w2r[nt].y, s1);
        }

        // quad reduction + stage
        s0 += __shfl_xor_sync(0xFFFFFFFF, s0, 1);
        s0 += __shfl_xor_sync(0xFFFFFFFF, s0, 2);
        s1 += __shfl_xor_sync(0xFFFFFFFF, s1, 1);
        s1 += __shfl_xor_sync(0xFFFFFFFF, s1, 2);
        if (lq == 0) {
            outs[(mt * 16 + lr) * G_NODES + warp] = s0;
            outs[(mt * 16 + lr + 8) * G_NODES + warp] = s1;
        }
    }
    __syncthreads();

    // --- coalesced store: 256 rows x 8 floats = 512 float4 ---
#pragma unroll
    for (int it = 0; it < 2; it++) {
        int idx = tid + it * 256;
        int r = idx >> 1, q = idx & 1;
        float4 v = ((const float4*)outs)[idx];
        *(float4*)(out + (size_t)(row0 + r) * N_VARS + group * G_NODES + q * 4) = v;
    }
}

// ---------------- launch ----------------
extern "C" void kernel_launch(void* const* d_in, const int* in_sizes, int n_in,
                              void* d_out, int out_size) {
    // metadata order: t, inputs, W1, W2, adjacency, discrete_mask
    const float* inputs = (const float*)d_in[1];
    const float* W1     = (const float*)d_in[2];
    const float* W2     = (const float*)d_in[3];
    const float* adj    = (const float*)d_in[4];
    float* out = (float*)d_out;

    static bool attr_set = false;
    if (!attr_set) {
        cudaFuncSetAttribute(main_kernel, cudaFuncAttributeMaxDynamicSharedMemorySize,
                             SM_TOTAL);
        attr_set = true;
    }

    cvt_kernel<<<(B_SZ * N_VARS / 8) / 256, 256>>>((const float4*)inputs);
    wfrag_kernel<<<256, 256>>>(W1, adj);
    main_kernel<<<dim3(BTILES, NODE_GROUPS), 256, SM_TOTAL>>>(W2, out);
}

// round 17
// speedup vs baseline: 1.1775x; 1.0484x over previous
#include <cuda_runtime.h>
#include <cuda_fp16.h>
#include <cstdint>

// Problem constants
#define B_SZ   32768
#define N_VARS 64
#define H_SZ   64
#define N_DISC 16
#define TILE_M 256          // batch rows per CTA
#define G_NODES 8           // nodes per CTA (one per warp)
#define NODE_GROUPS 8       // 64 / 8
#define BTILES (B_SZ / TILE_M)   // 128
#define MTILES (TILE_M / 16)     // 16

// X tile in smem: fp16, padded row stride 72 halves (144B) -> conflict-free ldmatrix
#define XS_STRIDE 72
#define XROW_B (XS_STRIDE * 2)   // 144

// smem layout (bytes)
#define SM_X    0
#define SM_X_SZ (TILE_M * XROW_B)                        // 36864
#define SM_W2   (SM_X + SM_X_SZ)                         // 36864
#define SM_W2_SZ (G_NODES * H_SZ * 4)                    // 2048
#define SM_OUT  (SM_W2 + SM_W2_SZ)                       // 38912
#define SM_OUT_SZ (TILE_M * G_NODES * 4)                 // 4096
#define SM_TOTAL (SM_OUT + SM_OUT_SZ)                    // 43008 (x2 CTAs = 86KB)

// Pre-swizzled fp16 B fragments: [node][ktile(4)][ntile(8)][lane(32)] x uint2
__device__ uint2 g_wfrag[(size_t)N_VARS * 4 * 8 * 32];

__device__ __forceinline__ uint32_t h2_as_u32(__half2 h) {
    union { __half2 h; uint32_t u; } cvt;
    cvt.h = h;
    return cvt.u;
}
__device__ __forceinline__ uint32_t smem_u32(const void* p) {
    uint32_t a;
    asm("{ .reg .u64 t; cvta.to.shared.u64 t, %1; cvt.u32.u64 %0, t; }" : "=r"(a) : "l"(p));
    return a;
}
__device__ __forceinline__ void ldmatrix_x4(uint32_t r[4], uint32_t addr) {
    asm volatile("ldmatrix.sync.aligned.m8n8.x4.shared.b16 {%0,%1,%2,%3}, [%4];"
                 : "=r"(r[0]), "=r"(r[1]), "=r"(r[2]), "=r"(r[3]) : "r"(addr));
}
__device__ __forceinline__ void mma16816(float c[4], const uint32_t a[4],
                                         uint32_t b0, uint32_t b1) {
    asm volatile(
        "mma.sync.aligned.m16n8k16.row.col.f32.f16.f16.f32 "
        "{%0,%1,%2,%3}, {%4,%5,%6,%7}, {%8,%9}, {%0,%1,%2,%3};"
        : "+f"(c[0]), "+f"(c[1]), "+f"(c[2]), "+f"(c[3])
        : "r"(a[0]), "r"(a[1]), "r"(a[2]), "r"(a[3]), "r"(b0), "r"(b1));
}
__device__ __forceinline__ uint32_t gate2(float x, float y, bool disc) {
    if (disc) {
        x = x > 0.f ? 1.f : 0.f;
        y = y > 0.f ? 1.f : 0.f;
    }
    return h2_as_u32(__floats2half2_rn(x, y));
}

// ---------------- prolog: build masked fp16 B fragments ----------------
__global__ void __launch_bounds__(256) wfrag_kernel(const float* __restrict__ W1,
                                                    const float* __restrict__ adj) {
    int idx = blockIdx.x * 256 + threadIdx.x;        // 65536 total
    int lane  = idx & 31;
    int ntile = (idx >> 5) & 7;
    int ktile = (idx >> 8) & 3;
    int node  = idx >> 10;
    int h  = ntile * 8 + (lane >> 2);
    int k0 = ktile * 16 + (lane & 3) * 2;

    const float* wrow = W1 + ((size_t)node * H_SZ + h) * N_VARS;
    float2 wlo = *(const float2*)(wrow + k0);
    float2 whi = *(const float2*)(wrow + k0 + 8);
    const float* arow = adj + node * N_VARS;
    float2 alo = *(const float2*)(arow + k0);
    float2 ahi = *(const float2*)(arow + k0 + 8);
    if (node == N_VARS - 1) {   // hidden_flag: last node keeps only feature 63
        alo.x = 0.f; alo.y = 0.f;
        ahi.x = 0.f;
        if (k0 + 9 != N_VARS - 1) ahi.y = 0.f;
    }
    uint2 r;
    r.x = h2_as_u32(__floats2half2_rn(wlo.x * alo.x, wlo.y * alo.y));
    r.y = h2_as_u32(__floats2half2_rn(whi.x * ahi.x, whi.y * ahi.y));
    g_wfrag[idx] = r;
}

// ---------------- main kernel ----------------
// One warp == one node; B tile (64x64 fp16) in 64 regs. X tile converted
// fp32 -> gated fp16 directly in the prologue (no separate cvt kernel).
__global__ void __launch_bounds__(256, 2)
main_kernel(const float4* __restrict__ in4, const float* __restrict__ W2,
            float* __restrict__ out) {
    extern __shared__ char smem[];
    const int tid = threadIdx.x;
    const int lane = tid & 31, warp = tid >> 5;   // warp = node-in-group
    const int group = blockIdx.y;
    const int row0 = blockIdx.x * TILE_M;

    float* w2s = (float*)(smem + SM_W2);
    float* outs = (float*)(smem + SM_OUT);

    // --- W2 for this group (512 floats) ---
    if (tid < 128)
        ((float4*)w2s)[tid] = ((const float4*)(W2 + group * G_NODES * H_SZ))[tid];

    // --- X tile: load fp32, gate discrete vars, convert fp16, store 16B chunks ---
    // chunk idx: row r = idx/8, 16B-chunk j = idx%8 (vars j*8..j*8+7)
#pragma unroll
    for (int it = 0; it < 8; it++) {
        int idx = tid + it * 256;             // 0..2047
        int r = idx >> 3, j = idx & 7;
        const float4* src = in4 + (size_t)(row0 + r) * 16 + j * 2;
        float4 v0 = src[0];
        float4 v1 = src[1];
        bool disc = (j * 8) < N_DISC;         // 16 % 8 == 0
        uint4 o;
        o.x = gate2(v0.x, v0.y, disc);
        o.y = gate2(v0.z, v0.w, disc);
        o.z = gate2(v1.x, v1.y, disc);
        o.w = gate2(v1.z, v1.w, disc);
        *(uint4*)(smem + SM_X + r * XROW_B + j * 16) = o;
    }

    // --- B fragments for this warp's node: 64 regs (precomputed, L2-resident) ---
    uint2 bf[4][8];
    {
        const uint2* src = g_wfrag + ((size_t)(group * G_NODES + warp) * 4) * 8 * 32 + lane;
#pragma unroll
        for (int kt = 0; kt < 4; kt++)
#pragma unroll
            for (int nt = 0; nt < 8; nt++)
                bf[kt][nt] = src[(kt * 8 + nt) * 32];
    }
    __syncthreads();

    const uint32_t xsb = smem_u32(smem) + SM_X;
    const int mtx = lane >> 3, rowm = lane & 7;
    const int lq = lane & 3;       // quad col id
    const int lr = lane >> 2;      // row-in-8
    const uint32_t arow_off = (uint32_t)(((mtx & 1) * 8 + rowm) * XROW_B
                                         + ((mtx >> 1) * 8) * 2);

    // --- W2 hoisted to registers: per-lane pair for each ntile ---
    float2 w2r[8];
#pragma unroll
    for (int nt = 0; nt < 8; nt++)
        w2r[nt] = *(const float2*)&w2s[warp * H_SZ + nt * 8 + lq * 2];

#pragma unroll 1
    for (int mt = 0; mt < MTILES; mt++) {
        const uint32_t mbase = xsb + (uint32_t)(mt * 16 * XROW_B) + arow_off;

        // all K=64 A fragments for this mtile (4 x ldmatrix.x4)
        uint32_t a[4][4];
#pragma unroll
        for (int kt = 0; kt < 4; kt++)
            ldmatrix_x4(a[kt], mbase + (uint32_t)(kt * 32));

        float s0 = 0.f, s1 = 0.f;
#pragma unroll
        for (int nt = 0; nt < 8; nt++) {
            float c[4] = {0.f, 0.f, 0.f, 0.f};
#pragma unroll
            for (int kt = 0; kt < 4; kt++)
                mma16816(c, a[kt], bf[kt][nt].x, bf[kt][nt].y);
            // fused epilogue for this ntile (overlaps next ntile's MMA chain)
            s0 = fmaf(fmaxf(c[0], 0.f), w2r[nt].x, s0);
            s0 = fmaf(fmaxf(c[1], 0.f), w2r[nt].y, s0);
            s1 = fmaf(fmaxf(c[2], 0.f), w2r[nt].x, s1);
            s1 = fmaf(fmaxf(c[3], 0.f), w2r[nt].y, s1);
        }

        // quad reduction + stage
        s0 += __shfl_xor_sync(0xFFFFFFFF, s0, 1);
        s0 += __shfl_xor_sync(0xFFFFFFFF, s0, 2);
        s1 += __shfl_xor_sync(0xFFFFFFFF, s1, 1);
        s1 += __shfl_xor_sync(0xFFFFFFFF, s1, 2);
        if (lq == 0) {
            outs[(mt * 16 + lr) * G_NODES + warp] = s0;
            outs[(mt * 16 + lr + 8) * G_NODES + warp] = s1;
        }
    }
    __syncthreads();

    // --- coalesced store: 256 rows x 8 floats = 512 float4 ---
#pragma unroll
    for (int it = 0; it < 2; it++) {
        int idx = tid + it * 256;
        int r = idx >> 1, q = idx & 1;
        float4 v = ((const float4*)outs)[idx];
        *(float4*)(out + (size_t)(row0 + r) * N_VARS + group * G_NODES + q * 4) = v;
    }
}

// ---------------- launch ----------------
extern "C" void kernel_launch(void* const* d_in, const int* in_sizes, int n_in,
                              void* d_out, int out_size) {
    // metadata order: t, inputs, W1, W2, adjacency, discrete_mask
    const float* inputs = (const float*)d_in[1];
    const float* W1     = (const float*)d_in[2];
    const float* W2     = (const float*)d_in[3];
    const float* adj    = (const float*)d_in[4];
    float* out = (float*)d_out;

    static bool attr_set = false;
    if (!attr_set) {
        cudaFuncSetAttribute(main_kernel, cudaFuncAttributeMaxDynamicSharedMemorySize,
                             SM_TOTAL);
        attr_set = true;
    }

    wfrag_kernel<<<256, 256>>>(W1, adj);
    main_kernel<<<dim3(BTILES, NODE_GROUPS), 256, SM_TOTAL>>>(
        (const float4*)inputs, W2, out);
}